// round 3
// baseline (speedup 1.0000x reference)
#include <cuda_runtime.h>
#include <math.h>
#include <stdint.h>

#define BB 64
#define TT 1024
#define INF 512
#define HH 768
#define GG 3072          // 4*H
#define MM (BB*TT)       // 65536
#define OUTD 100

// persistent-recurrence config
#define NCTA 128         // CTAs (1 per SM, all co-resident)
#define JC 6             // h-columns per CTA (128*6 = 768)
#define NC 24            // gate columns per CTA (4 gates * JC)
#define KC 64            // k chunk
#define NCH (HH/KC)      // 12 chunks
#define WPAD 776         // Wsh row stride (768+8): degree-2 banks, 16B aligned
#define HPAD 68          // Hs row stride (64+4):  16B aligned

// ---------------- scratch (device globals; no allocation allowed) ----------------
__device__ float g_pre[(size_t)MM * GG];   // [B*T, 4H]
__device__ float g_x1[(size_t)MM * HH];
__device__ float g_x2[(size_t)MM * HH];
__device__ float g_x3[(size_t)MM * HH];
__device__ float g_proj[(size_t)MM * 128]; // padded projection output
__device__ float g_wpad[128 * HH];         // zero-padded Wp
__device__ float g_h[2][BB * HH];          // double-buffered hidden state
__device__ float g_c[BB * HH];             // cell state
__device__ unsigned g_count = 0;           // grid barrier arrivals
__device__ unsigned g_epoch = 0;           // grid barrier epoch (monotonic)

// ---------------- cp.async helpers ----------------
__device__ __forceinline__ void cpasync16(uint32_t saddr, const void* g) {
    asm volatile("cp.async.cg.shared.global [%0], [%1], 16;\n" :: "r"(saddr), "l"(g));
}
__device__ __forceinline__ void cpcommit() { asm volatile("cp.async.commit_group;\n"); }
template<int N> __device__ __forceinline__ void cpwait() {
    asm volatile("cp.async.wait_group %0;\n" :: "n"(N));
}

// ---------------- software grid barrier ----------------
// release: every thread fences its global stores; acquire: spinner fences.
// e0-relative epoch comparison makes it robust across graph replays.
__device__ __forceinline__ void grid_barrier(unsigned e0, unsigned target) {
    __threadfence();
    __syncthreads();
    if (threadIdx.x == 0) {
        unsigned a = atomicAdd(&g_count, 1);
        if (a == NCTA - 1) {
            g_count = 0;
            __threadfence();
            atomicAdd(&g_epoch, 1);
        } else {
            while ((*(volatile unsigned*)&g_epoch) - e0 < target) { }
            __threadfence();
        }
    }
    __syncthreads();
}

// ---------------- C[M,N] = A[M,K] @ W[N,K]^T (+ bias[N]) ----------------
// tile 128x128, K-chunk 8, 256 threads, 8x8 micro, reg double-buffered loads
__global__ __launch_bounds__(256)
void sgemm_bias(const float* __restrict__ A, const float* __restrict__ W,
                const float* __restrict__ bias, float* __restrict__ C,
                int M, int N, int K)
{
    __shared__ float As[8][128];
    __shared__ float Bs[8][128];
    int tid = threadIdx.x;
    int m0 = blockIdx.y * 128;
    int n0 = blockIdx.x * 128;
    int tx = tid & 15;          // n-group
    int ty = tid >> 4;          // m-group
    int lr = tid >> 1;          // row within tile
    int lc = (tid & 1) * 4;     // k offset 0 or 4

    const float* Aptr = A + (size_t)(m0 + lr) * K + lc;
    const float* Bptr = W + (size_t)(n0 + lr) * K + lc;

    float acc[8][8];
#pragma unroll
    for (int i = 0; i < 8; i++)
#pragma unroll
        for (int j = 0; j < 8; j++) acc[i][j] = 0.f;

    float4 av = *(const float4*)(Aptr);
    float4 bv = *(const float4*)(Bptr);

    for (int k0 = 0; k0 < K; k0 += 8) {
        As[lc+0][lr] = av.x; As[lc+1][lr] = av.y; As[lc+2][lr] = av.z; As[lc+3][lr] = av.w;
        Bs[lc+0][lr] = bv.x; Bs[lc+1][lr] = bv.y; Bs[lc+2][lr] = bv.z; Bs[lc+3][lr] = bv.w;
        __syncthreads();
        if (k0 + 8 < K) {                 // prefetch next chunk during compute
            av = *(const float4*)(Aptr + k0 + 8);
            bv = *(const float4*)(Bptr + k0 + 8);
        }
#pragma unroll
        for (int k = 0; k < 8; k++) {
            float a_[8], b_[8];
            *(float4*)&a_[0] = *(const float4*)&As[k][ty*8];
            *(float4*)&a_[4] = *(const float4*)&As[k][ty*8 + 4];
            *(float4*)&b_[0] = *(const float4*)&Bs[k][tx*8];
            *(float4*)&b_[4] = *(const float4*)&Bs[k][tx*8 + 4];
#pragma unroll
            for (int i = 0; i < 8; i++)
#pragma unroll
                for (int j = 0; j < 8; j++)
                    acc[i][j] += a_[i] * b_[j];
        }
        __syncthreads();
    }

#pragma unroll
    for (int i = 0; i < 8; i++) {
        size_t row = (size_t)(m0 + ty*8 + i) * N + n0 + tx*8;
#pragma unroll
        for (int j = 0; j < 8; j += 4) {
            float4 v;
            v.x = acc[i][j+0]; v.y = acc[i][j+1]; v.z = acc[i][j+2]; v.w = acc[i][j+3];
            if (bias) {
                int nb = n0 + tx*8 + j;
                v.x += bias[nb+0]; v.y += bias[nb+1]; v.z += bias[nb+2]; v.w += bias[nb+3];
            }
            *(float4*)&C[row + j] = v;
        }
    }
}

// ---------------- persistent fused LSTM layer ----------------
// One launch per layer. 128 CTAs x 128 threads, all co-resident.
// CTA owns h-columns [j0, j0+JC). Whh slice cached in SMEM for the whole layer.
// h staged per 64-k chunk via double-buffered cp.async.cg (L2-coherent).
__device__ __forceinline__ void issue_chunk(float* dst, const float* hin, int k0, int tid) {
#pragma unroll
    for (int i = 0; i < 8; i++) {
        int idx = i * 128 + tid;      // 0..1023 float4s
        int b  = idx >> 4;            // 16 f4 per row
        int kq = idx & 15;
        cpasync16((uint32_t)__cvta_generic_to_shared(dst + b * HPAD + kq * 4),
                  hin + (size_t)b * HH + k0 + kq * 4);
    }
}

__global__ __launch_bounds__(128, 1)
void lstm_persist(const float* __restrict__ pre, const float* __restrict__ Whh,
                  float* __restrict__ h0g, float* __restrict__ h1g,
                  float* __restrict__ cst, float* __restrict__ y,
                  const float* __restrict__ res)
{
    extern __shared__ float sm[];
    float* Wsh = sm;                        // [NC][WPAD]
    float* Hsm = sm + NC * WPAD;            // [2][64][HPAD]
    float* Csm = Hsm + 2 * 64 * HPAD;       // [64][28]

    int tid = threadIdx.x;
    int j0 = blockIdx.x * JC;
    unsigned e0 = 0;
    if (tid == 0) e0 = *(volatile unsigned*)&g_epoch;

    // cache Whh slice: SMEM row r = gate g=r/JC, h-col j0+r%JC
    for (int i = tid; i < NC * (HH / 4); i += 128) {
        int r  = i / (HH / 4);
        int kq = i % (HH / 4);
        int g  = r / JC, jj = r % JC;
        float4 v = *(const float4*)&Whh[(size_t)(g * HH + j0 + jj) * HH + kq * 4];
        *(float4*)&Wsh[r * WPAD + kq * 4] = v;
    }

    // zero owned columns of h (parity-0 buffer) and c
    if (tid < BB) {
#pragma unroll
        for (int jj = 0; jj < JC; jj++) {
            h0g[tid * HH + j0 + jj] = 0.f;
            cst[tid * HH + j0 + jj] = 0.f;
        }
    }
    grid_barrier(e0, 1);

    int bg = tid >> 3;   // 0..15 -> batch rows bg*4..bg*4+3
    int ng = tid & 7;    // 0..7  -> gate cols ng*3..ng*3+2

    for (int t = 0; t < TT; t++) {
        const float* hin = (t & 1) ? h1g : h0g;
        float*       hout = (t & 1) ? h0g : h1g;

        issue_chunk(Hsm, hin, 0, tid);
        cpcommit();

        float acc[4][3];
#pragma unroll
        for (int i = 0; i < 4; i++)
#pragma unroll
            for (int j = 0; j < 3; j++) acc[i][j] = 0.f;

        int buf = 0;
        for (int c = 0; c < NCH; c++) {
            if (c + 1 < NCH) {
                issue_chunk(Hsm + (buf ^ 1) * 64 * HPAD, hin, (c + 1) * KC, tid);
                cpcommit();
                cpwait<1>();
            } else {
                cpwait<0>();
            }
            __syncthreads();
            const float* H = Hsm + buf * 64 * HPAD;
            const int kbase = c * KC;
#pragma unroll 4
            for (int k = 0; k < KC; k += 4) {
                float4 wv0 = *(const float4*)&Wsh[(ng*3+0) * WPAD + kbase + k];
                float4 wv1 = *(const float4*)&Wsh[(ng*3+1) * WPAD + kbase + k];
                float4 wv2 = *(const float4*)&Wsh[(ng*3+2) * WPAD + kbase + k];
                float4 h0v = *(const float4*)&H[(bg*4+0) * HPAD + k];
                float4 h1v = *(const float4*)&H[(bg*4+1) * HPAD + k];
                float4 h2v = *(const float4*)&H[(bg*4+2) * HPAD + k];
                float4 h3v = *(const float4*)&H[(bg*4+3) * HPAD + k];
                acc[0][0] += h0v.x*wv0.x + h0v.y*wv0.y + h0v.z*wv0.z + h0v.w*wv0.w;
                acc[0][1] += h0v.x*wv1.x + h0v.y*wv1.y + h0v.z*wv1.z + h0v.w*wv1.w;
                acc[0][2] += h0v.x*wv2.x + h0v.y*wv2.y + h0v.z*wv2.z + h0v.w*wv2.w;
                acc[1][0] += h1v.x*wv0.x + h1v.y*wv0.y + h1v.z*wv0.z + h1v.w*wv0.w;
                acc[1][1] += h1v.x*wv1.x + h1v.y*wv1.y + h1v.z*wv1.z + h1v.w*wv1.w;
                acc[1][2] += h1v.x*wv2.x + h1v.y*wv2.y + h1v.z*wv2.z + h1v.w*wv2.w;
                acc[2][0] += h2v.x*wv0.x + h2v.y*wv0.y + h2v.z*wv0.z + h2v.w*wv0.w;
                acc[2][1] += h2v.x*wv1.x + h2v.y*wv1.y + h2v.z*wv1.z + h2v.w*wv1.w;
                acc[2][2] += h2v.x*wv2.x + h2v.y*wv2.y + h2v.z*wv2.z + h2v.w*wv2.w;
                acc[3][0] += h3v.x*wv0.x + h3v.y*wv0.y + h3v.z*wv0.z + h3v.w*wv0.w;
                acc[3][1] += h3v.x*wv1.x + h3v.y*wv1.y + h3v.z*wv1.z + h3v.w*wv1.w;
                acc[3][2] += h3v.x*wv2.x + h3v.y*wv2.y + h3v.z*wv2.z + h3v.w*wv2.w;
            }
            __syncthreads();
            buf ^= 1;
        }

        // stash gate tile
#pragma unroll
        for (int r = 0; r < 4; r++)
#pragma unroll
            for (int cc = 0; cc < 3; cc++)
                Csm[(bg*4 + r) * 28 + ng*3 + cc] = acc[r][cc];
        __syncthreads();

        // cell update: 64 b x JC cols = 384 elements, 3 per thread
#pragma unroll
        for (int r = 0; r < 3; r++) {
            int e = r * 128 + tid;
            int b = e / JC, jj = e % JC;
            int j = j0 + jj;
            size_t prow = ((size_t)b * TT + t) * GG;
            float gi = Csm[b*28 + 0*JC + jj] + pre[prow + 0*HH + j];
            float gf = Csm[b*28 + 1*JC + jj] + pre[prow + 1*HH + j];
            float gg = Csm[b*28 + 2*JC + jj] + pre[prow + 2*HH + j];
            float go = Csm[b*28 + 3*JC + jj] + pre[prow + 3*HH + j];
            float si = 1.0f / (1.0f + expf(-gi));
            float sf = 1.0f / (1.0f + expf(-gf));
            float so = 1.0f / (1.0f + expf(-go));
            float tg = tanhf(gg);
            int ci = b * HH + j;
            float cn = sf * cst[ci] + si * tg;
            float hn = so * tanhf(cn);
            cst[ci] = cn;
            hout[ci] = hn;
            size_t yi = ((size_t)b * TT + t) * HH + j;
            y[yi] = res ? hn + res[yi] : hn;   // fused residual
        }
        grid_barrier(e0, t + 2);
    }
}

// ---------------- small helpers ----------------
__global__ void pad_wp(float* __restrict__ wpad, const float* __restrict__ Wp)
{
    int i = blockIdx.x * blockDim.x + threadIdx.x;
    int stride = gridDim.x * blockDim.x;
    for (; i < 128 * HH; i += stride) {
        int o = i / HH, k = i % HH;
        wpad[i] = (o < OUTD) ? Wp[o * HH + k] : 0.f;
    }
}

__global__ void copy_out(float* __restrict__ out, const float* __restrict__ proj, int n)
{
    int i = blockIdx.x * blockDim.x + threadIdx.x;
    int stride = gridDim.x * blockDim.x;
    for (; i < n; i += stride) {
        int m = i / OUTD, o = i % OUTD;
        out[i] = proj[(size_t)m * 128 + o];
    }
}

// ---------------- driver (9 graph nodes) ----------------
extern "C" void kernel_launch(void* const* d_in, const int* in_sizes, int n_in,
                              void* d_out, int out_size)
{
    const float* x   = (const float*)d_in[0];
    const float* Wih[3] = { (const float*)d_in[1], (const float*)d_in[4], (const float*)d_in[7] };
    const float* Whh[3] = { (const float*)d_in[2], (const float*)d_in[5], (const float*)d_in[8] };
    const float* bgt[3] = { (const float*)d_in[3], (const float*)d_in[6], (const float*)d_in[9] };
    const float* Wp  = (const float*)d_in[10];

    float *pre, *x1, *x2, *x3, *proj, *wpad, *hbuf, *cbuf;
    cudaGetSymbolAddress((void**)&pre,  g_pre);
    cudaGetSymbolAddress((void**)&x1,   g_x1);
    cudaGetSymbolAddress((void**)&x2,   g_x2);
    cudaGetSymbolAddress((void**)&x3,   g_x3);
    cudaGetSymbolAddress((void**)&proj, g_proj);
    cudaGetSymbolAddress((void**)&wpad, g_wpad);
    cudaGetSymbolAddress((void**)&hbuf, g_h);
    cudaGetSymbolAddress((void**)&cbuf, g_c);
    float* h0 = hbuf;
    float* h1 = hbuf + BB * HH;

    const int SMEM = (NC * WPAD + 2 * 64 * HPAD + 64 * 28) * sizeof(float);
    cudaFuncSetAttribute(lstm_persist, cudaFuncAttributeMaxDynamicSharedMemorySize, SMEM);

    float* xs[3] = { x1, x2, x3 };
    const float* layerIn = x;
    int K = INF;

    for (int L = 0; L < 3; L++) {
        dim3 grid(GG / 128, MM / 128);
        sgemm_bias<<<grid, 256>>>(layerIn, Wih[L], bgt[L], pre, MM, GG, K);

        const float* res = (L > 0) ? layerIn : nullptr;
        lstm_persist<<<NCTA, 128, SMEM>>>(pre, Whh[L], h0, h1, cbuf, xs[L], res);

        layerIn = xs[L];
        K = HH;
    }

    pad_wp<<<96, 256>>>(wpad, Wp);
    dim3 gridP(1, MM / 128);
    sgemm_bias<<<gridP, 256>>>(x3, wpad, nullptr, proj, MM, 128, HH);
    copy_out<<<1024, 256>>>((float*)d_out, proj, MM * OUTD);
}

// round 4
// speedup vs baseline: 1.0009x; 1.0009x over previous
#include <cuda_runtime.h>
#include <math.h>
#include <stdint.h>

#define BB 64
#define TT 1024
#define INF 512
#define HH 768
#define GG 3072          // 4*H
#define MM (BB*TT)       // 65536
#define OUTD 100

// persistent-recurrence config
#define NCTA 128         // CTAs (1 per SM, all co-resident)
#define JC 6             // h-columns per CTA (128*6 = 768)
#define NC 24            // gate columns per CTA (4 gates * JC)
#define KC 64            // k chunk
#define NCH (HH/KC)      // 12 chunks
#define WPAD 776         // Wsh row stride (768+8): degree-2 banks, 16B aligned
#define HPAD 68          // Hs row stride (64+4):  16B aligned

// ---------------- scratch (device globals; no allocation allowed) ----------------
__device__ float g_pre[(size_t)MM * GG];   // [B*T, 4H]
__device__ float g_x1[(size_t)MM * HH];
__device__ float g_x2[(size_t)MM * HH];
__device__ float g_x3[(size_t)MM * HH];
__device__ float g_proj[(size_t)MM * 128]; // padded projection output
__device__ float g_wpad[128 * HH];         // zero-padded Wp
__device__ float g_h[2][BB * HH];          // double-buffered hidden state
__device__ float g_c[BB * HH];             // cell state
__device__ unsigned g_count = 0;           // grid barrier arrivals
__device__ unsigned g_epoch = 0;           // grid barrier epoch (monotonic)

// ---------------- cp.async helpers ----------------
__device__ __forceinline__ void cpasync16(uint32_t saddr, const void* g) {
    asm volatile("cp.async.cg.shared.global [%0], [%1], 16;\n" :: "r"(saddr), "l"(g));
}
__device__ __forceinline__ void cpcommit() { asm volatile("cp.async.commit_group;\n"); }
template<int N> __device__ __forceinline__ void cpwait() {
    asm volatile("cp.async.wait_group %0;\n" :: "n"(N));
}

// ---------------- software grid barrier ----------------
// release: every thread fences its global stores; acquire: spinner fences.
// e0-relative epoch comparison makes it robust across graph replays.
__device__ __forceinline__ void grid_barrier(unsigned e0, unsigned target) {
    __threadfence();
    __syncthreads();
    if (threadIdx.x == 0) {
        unsigned a = atomicAdd(&g_count, 1);
        if (a == NCTA - 1) {
            g_count = 0;
            __threadfence();
            atomicAdd(&g_epoch, 1);
        } else {
            while ((*(volatile unsigned*)&g_epoch) - e0 < target) { }
            __threadfence();
        }
    }
    __syncthreads();
}

// ---------------- C[M,N] = A[M,K] @ W[N,K]^T (+ bias[N]) ----------------
// tile 128x128, K-chunk 8, 256 threads, 8x8 micro, reg double-buffered loads
__global__ __launch_bounds__(256)
void sgemm_bias(const float* __restrict__ A, const float* __restrict__ W,
                const float* __restrict__ bias, float* __restrict__ C,
                int M, int N, int K)
{
    __shared__ float As[8][128];
    __shared__ float Bs[8][128];
    int tid = threadIdx.x;
    int m0 = blockIdx.y * 128;
    int n0 = blockIdx.x * 128;
    int tx = tid & 15;          // n-group
    int ty = tid >> 4;          // m-group
    int lr = tid >> 1;          // row within tile
    int lc = (tid & 1) * 4;     // k offset 0 or 4

    const float* Aptr = A + (size_t)(m0 + lr) * K + lc;
    const float* Bptr = W + (size_t)(n0 + lr) * K + lc;

    float acc[8][8];
#pragma unroll
    for (int i = 0; i < 8; i++)
#pragma unroll
        for (int j = 0; j < 8; j++) acc[i][j] = 0.f;

    float4 av = *(const float4*)(Aptr);
    float4 bv = *(const float4*)(Bptr);

    for (int k0 = 0; k0 < K; k0 += 8) {
        As[lc+0][lr] = av.x; As[lc+1][lr] = av.y; As[lc+2][lr] = av.z; As[lc+3][lr] = av.w;
        Bs[lc+0][lr] = bv.x; Bs[lc+1][lr] = bv.y; Bs[lc+2][lr] = bv.z; Bs[lc+3][lr] = bv.w;
        __syncthreads();
        if (k0 + 8 < K) {                 // prefetch next chunk during compute
            av = *(const float4*)(Aptr + k0 + 8);
            bv = *(const float4*)(Bptr + k0 + 8);
        }
#pragma unroll
        for (int k = 0; k < 8; k++) {
            float a_[8], b_[8];
            *(float4*)&a_[0] = *(const float4*)&As[k][ty*8];
            *(float4*)&a_[4] = *(const float4*)&As[k][ty*8 + 4];
            *(float4*)&b_[0] = *(const float4*)&Bs[k][tx*8];
            *(float4*)&b_[4] = *(const float4*)&Bs[k][tx*8 + 4];
#pragma unroll
            for (int i = 0; i < 8; i++)
#pragma unroll
                for (int j = 0; j < 8; j++)
                    acc[i][j] += a_[i] * b_[j];
        }
        __syncthreads();
    }

#pragma unroll
    for (int i = 0; i < 8; i++) {
        size_t row = (size_t)(m0 + ty*8 + i) * N + n0 + tx*8;
#pragma unroll
        for (int j = 0; j < 8; j += 4) {
            float4 v;
            v.x = acc[i][j+0]; v.y = acc[i][j+1]; v.z = acc[i][j+2]; v.w = acc[i][j+3];
            if (bias) {
                int nb = n0 + tx*8 + j;
                v.x += bias[nb+0]; v.y += bias[nb+1]; v.z += bias[nb+2]; v.w += bias[nb+3];
            }
            *(float4*)&C[row + j] = v;
        }
    }
}

// ---------------- persistent fused LSTM layer ----------------
// One launch per layer. 128 CTAs x 128 threads, all co-resident.
// CTA owns h-columns [j0, j0+JC). Whh slice cached in SMEM for the whole layer.
// h staged per 64-k chunk via double-buffered cp.async.cg (L2-coherent).
__device__ __forceinline__ void issue_chunk(float* dst, const float* hin, int k0, int tid) {
#pragma unroll
    for (int i = 0; i < 8; i++) {
        int idx = i * 128 + tid;      // 0..1023 float4s
        int b  = idx >> 4;            // 16 f4 per row
        int kq = idx & 15;
        cpasync16((uint32_t)__cvta_generic_to_shared(dst + b * HPAD + kq * 4),
                  hin + (size_t)b * HH + k0 + kq * 4);
    }
}

__global__ __launch_bounds__(128, 1)
void lstm_persist(const float* __restrict__ pre, const float* __restrict__ Whh,
                  float* __restrict__ h0g, float* __restrict__ h1g,
                  float* __restrict__ cst, float* __restrict__ y,
                  const float* __restrict__ res)
{
    extern __shared__ float sm[];
    float* Wsh = sm;                        // [NC][WPAD]
    float* Hsm = sm + NC * WPAD;            // [2][64][HPAD]
    float* Csm = Hsm + 2 * 64 * HPAD;       // [64][28]

    int tid = threadIdx.x;
    int j0 = blockIdx.x * JC;
    unsigned e0 = 0;
    if (tid == 0) e0 = *(volatile unsigned*)&g_epoch;

    // cache Whh slice: SMEM row r = gate g=r/JC, h-col j0+r%JC
    for (int i = tid; i < NC * (HH / 4); i += 128) {
        int r  = i / (HH / 4);
        int kq = i % (HH / 4);
        int g  = r / JC, jj = r % JC;
        float4 v = *(const float4*)&Whh[(size_t)(g * HH + j0 + jj) * HH + kq * 4];
        *(float4*)&Wsh[r * WPAD + kq * 4] = v;
    }

    // zero owned columns of h (parity-0 buffer) and c
    if (tid < BB) {
#pragma unroll
        for (int jj = 0; jj < JC; jj++) {
            h0g[tid * HH + j0 + jj] = 0.f;
            cst[tid * HH + j0 + jj] = 0.f;
        }
    }
    grid_barrier(e0, 1);

    int bg = tid >> 3;   // 0..15 -> batch rows bg*4..bg*4+3
    int ng = tid & 7;    // 0..7  -> gate cols ng*3..ng*3+2

    for (int t = 0; t < TT; t++) {
        const float* hin = (t & 1) ? h1g : h0g;
        float*       hout = (t & 1) ? h0g : h1g;

        issue_chunk(Hsm, hin, 0, tid);
        cpcommit();

        float acc[4][3];
#pragma unroll
        for (int i = 0; i < 4; i++)
#pragma unroll
            for (int j = 0; j < 3; j++) acc[i][j] = 0.f;

        int buf = 0;
        for (int c = 0; c < NCH; c++) {
            if (c + 1 < NCH) {
                issue_chunk(Hsm + (buf ^ 1) * 64 * HPAD, hin, (c + 1) * KC, tid);
                cpcommit();
                cpwait<1>();
            } else {
                cpwait<0>();
            }
            __syncthreads();
            const float* H = Hsm + buf * 64 * HPAD;
            const int kbase = c * KC;
#pragma unroll 4
            for (int k = 0; k < KC; k += 4) {
                float4 wv0 = *(const float4*)&Wsh[(ng*3+0) * WPAD + kbase + k];
                float4 wv1 = *(const float4*)&Wsh[(ng*3+1) * WPAD + kbase + k];
                float4 wv2 = *(const float4*)&Wsh[(ng*3+2) * WPAD + kbase + k];
                float4 h0v = *(const float4*)&H[(bg*4+0) * HPAD + k];
                float4 h1v = *(const float4*)&H[(bg*4+1) * HPAD + k];
                float4 h2v = *(const float4*)&H[(bg*4+2) * HPAD + k];
                float4 h3v = *(const float4*)&H[(bg*4+3) * HPAD + k];
                acc[0][0] += h0v.x*wv0.x + h0v.y*wv0.y + h0v.z*wv0.z + h0v.w*wv0.w;
                acc[0][1] += h0v.x*wv1.x + h0v.y*wv1.y + h0v.z*wv1.z + h0v.w*wv1.w;
                acc[0][2] += h0v.x*wv2.x + h0v.y*wv2.y + h0v.z*wv2.z + h0v.w*wv2.w;
                acc[1][0] += h1v.x*wv0.x + h1v.y*wv0.y + h1v.z*wv0.z + h1v.w*wv0.w;
                acc[1][1] += h1v.x*wv1.x + h1v.y*wv1.y + h1v.z*wv1.z + h1v.w*wv1.w;
                acc[1][2] += h1v.x*wv2.x + h1v.y*wv2.y + h1v.z*wv2.z + h1v.w*wv2.w;
                acc[2][0] += h2v.x*wv0.x + h2v.y*wv0.y + h2v.z*wv0.z + h2v.w*wv0.w;
                acc[2][1] += h2v.x*wv1.x + h2v.y*wv1.y + h2v.z*wv1.z + h2v.w*wv1.w;
                acc[2][2] += h2v.x*wv2.x + h2v.y*wv2.y + h2v.z*wv2.z + h2v.w*wv2.w;
                acc[3][0] += h3v.x*wv0.x + h3v.y*wv0.y + h3v.z*wv0.z + h3v.w*wv0.w;
                acc[3][1] += h3v.x*wv1.x + h3v.y*wv1.y + h3v.z*wv1.z + h3v.w*wv1.w;
                acc[3][2] += h3v.x*wv2.x + h3v.y*wv2.y + h3v.z*wv2.z + h3v.w*wv2.w;
            }
            __syncthreads();
            buf ^= 1;
        }

        // stash gate tile
#pragma unroll
        for (int r = 0; r < 4; r++)
#pragma unroll
            for (int cc = 0; cc < 3; cc++)
                Csm[(bg*4 + r) * 28 + ng*3 + cc] = acc[r][cc];
        __syncthreads();

        // cell update: 64 b x JC cols = 384 elements, 3 per thread
#pragma unroll
        for (int r = 0; r < 3; r++) {
            int e = r * 128 + tid;
            int b = e / JC, jj = e % JC;
            int j = j0 + jj;
            size_t prow = ((size_t)b * TT + t) * GG;
            float gi = Csm[b*28 + 0*JC + jj] + pre[prow + 0*HH + j];
            float gf = Csm[b*28 + 1*JC + jj] + pre[prow + 1*HH + j];
            float gg = Csm[b*28 + 2*JC + jj] + pre[prow + 2*HH + j];
            float go = Csm[b*28 + 3*JC + jj] + pre[prow + 3*HH + j];
            float si = 1.0f / (1.0f + expf(-gi));
            float sf = 1.0f / (1.0f + expf(-gf));
            float so = 1.0f / (1.0f + expf(-go));
            float tg = tanhf(gg);
            int ci = b * HH + j;
            float cn = sf * cst[ci] + si * tg;
            float hn = so * tanhf(cn);
            cst[ci] = cn;
            hout[ci] = hn;
            size_t yi = ((size_t)b * TT + t) * HH + j;
            y[yi] = res ? hn + res[yi] : hn;   // fused residual
        }
        grid_barrier(e0, t + 2);
    }
}

// ---------------- small helpers ----------------
__global__ void pad_wp(float* __restrict__ wpad, const float* __restrict__ Wp)
{
    int i = blockIdx.x * blockDim.x + threadIdx.x;
    int stride = gridDim.x * blockDim.x;
    for (; i < 128 * HH; i += stride) {
        int o = i / HH, k = i % HH;
        wpad[i] = (o < OUTD) ? Wp[o * HH + k] : 0.f;
    }
}

__global__ void copy_out(float* __restrict__ out, const float* __restrict__ proj, int n)
{
    int i = blockIdx.x * blockDim.x + threadIdx.x;
    int stride = gridDim.x * blockDim.x;
    for (; i < n; i += stride) {
        int m = i / OUTD, o = i % OUTD;
        out[i] = proj[(size_t)m * 128 + o];
    }
}

// ---------------- driver (9 graph nodes) ----------------
extern "C" void kernel_launch(void* const* d_in, const int* in_sizes, int n_in,
                              void* d_out, int out_size)
{
    const float* x   = (const float*)d_in[0];
    const float* Wih[3] = { (const float*)d_in[1], (const float*)d_in[4], (const float*)d_in[7] };
    const float* Whh[3] = { (const float*)d_in[2], (const float*)d_in[5], (const float*)d_in[8] };
    const float* bgt[3] = { (const float*)d_in[3], (const float*)d_in[6], (const float*)d_in[9] };
    const float* Wp  = (const float*)d_in[10];

    float *pre, *x1, *x2, *x3, *proj, *wpad, *hbuf, *cbuf;
    cudaGetSymbolAddress((void**)&pre,  g_pre);
    cudaGetSymbolAddress((void**)&x1,   g_x1);
    cudaGetSymbolAddress((void**)&x2,   g_x2);
    cudaGetSymbolAddress((void**)&x3,   g_x3);
    cudaGetSymbolAddress((void**)&proj, g_proj);
    cudaGetSymbolAddress((void**)&wpad, g_wpad);
    cudaGetSymbolAddress((void**)&hbuf, g_h);
    cudaGetSymbolAddress((void**)&cbuf, g_c);
    float* h0 = hbuf;
    float* h1 = hbuf + BB * HH;

    const int SMEM = (NC * WPAD + 2 * 64 * HPAD + 64 * 28) * sizeof(float);
    cudaFuncSetAttribute(lstm_persist, cudaFuncAttributeMaxDynamicSharedMemorySize, SMEM);

    float* xs[3] = { x1, x2, x3 };
    const float* layerIn = x;
    int K = INF;

    for (int L = 0; L < 3; L++) {
        dim3 grid(GG / 128, MM / 128);
        sgemm_bias<<<grid, 256>>>(layerIn, Wih[L], bgt[L], pre, MM, GG, K);

        const float* res = (L > 0) ? layerIn : nullptr;
        lstm_persist<<<NCTA, 128, SMEM>>>(pre, Whh[L], h0, h1, cbuf, xs[L], res);

        layerIn = xs[L];
        K = HH;
    }

    pad_wp<<<96, 256>>>(wpad, Wp);
    dim3 gridP(1, MM / 128);
    sgemm_bias<<<gridP, 256>>>(x3, wpad, nullptr, proj, MM, 128, HH);
    copy_out<<<1024, 256>>>((float*)d_out, proj, MM * OUTD);
}

// round 6
// speedup vs baseline: 1.9818x; 1.9800x over previous
#include <cuda_runtime.h>
#include <cuda_bf16.h>
#include <math.h>
#include <stdint.h>

#define BB 64
#define TT 1024
#define INF 512
#define HH 768
#define GG 3072          // 4*H
#define MM (BB*TT)       // 65536
#define OUTD 100
#define BBHH (BB*HH)

// recurrence config
#define NCTA 128
#define JC 6             // h columns per CTA
#define NC 24            // gate rows per CTA (4*JC)
#define NCHR 12          // 768/64 k-chunks
#define WROWB 1552       // W smem row pitch bytes (768*2 + 16) -> conflict-free ldmatrix
#define HROWB 144        // h tile row pitch bytes (64*2 + 16)  -> conflict-free ldmatrix
#define HTILE (64*HROWB) // 9216
#define WTILE (NC*WROWB) // 37248

// GEMM config
#define GAT (128*HROWB)  // 18432 bytes: one 128x64 bf16 tile, 144B pitch
#define GSMEM (4*GAT)    // 2 buffers x (A,B)
#define RSMEM (2*WTILE + 4*HTILE + 64*28*4)   // 118528

// ---------------- scratch (device globals; no allocation allowed) ----------------
__device__ float g_pre[(size_t)MM * GG];
__device__ float g_x1[(size_t)MM * HH];
__device__ float g_x2[(size_t)MM * HH];
__device__ float g_x3[(size_t)MM * HH];
__device__ float g_proj[(size_t)MM * 128];
__device__ float g_c[BBHH];
__device__ __nv_bfloat16 g_hb[2][2][BBHH];   // [parity][hi/lo]
__device__ unsigned g_count = 0;
__device__ unsigned g_epoch = 0;
// bf16 split buffers
__device__ __nv_bfloat16 g_ah[(size_t)MM * HH];
__device__ __nv_bfloat16 g_al[(size_t)MM * HH];
__device__ __nv_bfloat16 g_bh[(size_t)GG * HH];
__device__ __nv_bfloat16 g_bl[(size_t)GG * HH];
__device__ __nv_bfloat16 g_ph[128 * HH];
__device__ __nv_bfloat16 g_pl[128 * HH];

// ---------------- ptx helpers (base sm_103 ISA only) ----------------
__device__ __forceinline__ void cpasync16(uint32_t saddr, const void* g) {
    asm volatile("cp.async.cg.shared.global [%0], [%1], 16;\n" :: "r"(saddr), "l"(g));
}
__device__ __forceinline__ void cpcommit() { asm volatile("cp.async.commit_group;\n"); }
template<int N> __device__ __forceinline__ void cpwait() {
    asm volatile("cp.async.wait_group %0;\n" :: "n"(N));
}
__device__ __forceinline__ uint32_t smem_u32(const void* p) {
    return (uint32_t)__cvta_generic_to_shared(p);
}
__device__ __forceinline__ void ldsm4(uint32_t addr, uint32_t* r) {
    asm volatile("ldmatrix.sync.aligned.m8n8.x4.shared.b16 {%0,%1,%2,%3}, [%4];"
                 : "=r"(r[0]), "=r"(r[1]), "=r"(r[2]), "=r"(r[3]) : "r"(addr));
}
__device__ __forceinline__ void ldsm2(uint32_t addr, uint32_t* r) {
    asm volatile("ldmatrix.sync.aligned.m8n8.x2.shared.b16 {%0,%1}, [%2];"
                 : "=r"(r[0]), "=r"(r[1]) : "r"(addr));
}
__device__ __forceinline__ void mma_bf16(float* d, const uint32_t* a, uint32_t b0, uint32_t b1) {
    asm volatile(
        "mma.sync.aligned.m16n8k16.row.col.f32.bf16.bf16.f32 "
        "{%0,%1,%2,%3}, {%4,%5,%6,%7}, {%8,%9}, {%0,%1,%2,%3};"
        : "+f"(d[0]), "+f"(d[1]), "+f"(d[2]), "+f"(d[3])
        : "r"(a[0]), "r"(a[1]), "r"(a[2]), "r"(a[3]), "r"(b0), "r"(b1));
}

// ---------------- software grid barrier ----------------
__device__ __forceinline__ void grid_barrier(unsigned e0, unsigned target) {
    __threadfence();
    __syncthreads();
    if (threadIdx.x == 0) {
        unsigned a = atomicAdd(&g_count, 1);
        if (a == NCTA - 1) {
            g_count = 0;
            __threadfence();
            atomicAdd(&g_epoch, 1);
        } else {
            while ((*(volatile unsigned*)&g_epoch) - e0 < target) { }
            __threadfence();
        }
    }
    __syncthreads();
}

// ---------------- bf16 split conversions ----------------
__global__ void split_bf16(const float* __restrict__ src,
                           __nv_bfloat16* __restrict__ hi,
                           __nv_bfloat16* __restrict__ lo, size_t n4)
{
    size_t i = (size_t)blockIdx.x * blockDim.x + threadIdx.x;
    size_t stride = (size_t)gridDim.x * blockDim.x;
    for (; i < n4; i += stride) {
        float4 v = ((const float4*)src)[i];
        __nv_bfloat16 h0 = __float2bfloat16(v.x);
        __nv_bfloat16 h1 = __float2bfloat16(v.y);
        __nv_bfloat16 h2 = __float2bfloat16(v.z);
        __nv_bfloat16 h3 = __float2bfloat16(v.w);
        __nv_bfloat162 hp0; hp0.x = h0; hp0.y = h1;
        __nv_bfloat162 hp1; hp1.x = h2; hp1.y = h3;
        __nv_bfloat162 lp0;
        lp0.x = __float2bfloat16(v.x - __bfloat162float(h0));
        lp0.y = __float2bfloat16(v.y - __bfloat162float(h1));
        __nv_bfloat162 lp1;
        lp1.x = __float2bfloat16(v.z - __bfloat162float(h2));
        lp1.y = __float2bfloat16(v.w - __bfloat162float(h3));
        ((__nv_bfloat162*)hi)[2*i]   = hp0;
        ((__nv_bfloat162*)hi)[2*i+1] = hp1;
        ((__nv_bfloat162*)lo)[2*i]   = lp0;
        ((__nv_bfloat162*)lo)[2*i+1] = lp1;
    }
}

__global__ void pad_wp_split(__nv_bfloat16* __restrict__ ph,
                             __nv_bfloat16* __restrict__ pl,
                             const float* __restrict__ Wp)
{
    int i = blockIdx.x * blockDim.x + threadIdx.x;
    int stride = gridDim.x * blockDim.x;
    for (; i < 128 * HH; i += stride) {
        int o = i / HH, k = i % HH;
        float v = (o < OUTD) ? Wp[o * HH + k] : 0.f;
        __nv_bfloat16 h = __float2bfloat16(v);
        ph[i] = h;
        pl[i] = __float2bfloat16(v - __bfloat162float(h));
    }
}

// ---------------- bf16x3 GEMM via mma.sync ----------------
// C[M,Ntot] = Ah@Bh^T + Ah@Bl^T + Al@Bh^T (+bias). A:[M,K] B:[Ntot,K] bf16.
// 256 thr = 8 warps (4m x 2n), warp tile 32x64, CTA tile 128x128, BK=64.
__device__ __forceinline__ void gemm_issue(uint32_t sb, int buf,
                                           const __nv_bfloat16* Ag,
                                           const __nv_bfloat16* Bg,
                                           int K, int tid)
{
    uint32_t dA = sb + buf * 2 * GAT;
    uint32_t dB = dA + GAT;
#pragma unroll
    for (int it = 0; it < 4; it++) {
        int idx = it * 256 + tid;
        int row = idx >> 3, seg = idx & 7;
        cpasync16(dA + row * HROWB + seg * 16, Ag + (size_t)row * K + seg * 8);
    }
#pragma unroll
    for (int it = 0; it < 4; it++) {
        int idx = it * 256 + tid;
        int row = idx >> 3, seg = idx & 7;
        cpasync16(dB + row * HROWB + seg * 16, Bg + (size_t)row * K + seg * 8);
    }
    cpcommit();
}

__global__ __launch_bounds__(256)
void gemm_mma3(const __nv_bfloat16* __restrict__ Ah, const __nv_bfloat16* __restrict__ Al,
               const __nv_bfloat16* __restrict__ Bh, const __nv_bfloat16* __restrict__ Bl,
               const float* __restrict__ bias, float* __restrict__ C,
               int K, int Ntot)
{
    extern __shared__ __align__(128) char gsm[];
    uint32_t sb = smem_u32(gsm);

    int tid = threadIdx.x;
    int lane = tid & 31;
    int wid = tid >> 5;
    int wm = wid & 3;          // m group (rows wm*32)
    int wn = wid >> 2;         // n group (cols wn*64)
    int m0 = blockIdx.y * 128;
    int n0 = blockIdx.x * 128;

    const __nv_bfloat16* As_[3] = { Ah, Ah, Al };
    const __nv_bfloat16* Bs_[3] = { Bh, Bl, Bh };
    const int cps = K >> 6;
    const int nch = 3 * cps;

    float acc[2][8][4];
#pragma unroll
    for (int mt = 0; mt < 2; mt++)
#pragma unroll
        for (int f = 0; f < 8; f++)
#pragma unroll
            for (int r = 0; r < 4; r++) acc[mt][f][r] = 0.f;

    // per-thread ldmatrix address components
    int aRow = (lane & 15);
    int aHalf = (lane >> 4) * 16;
    int gB = lane >> 3;
    int bHalf = (gB & 1) * 16;

    gemm_issue(sb, 0, As_[0] + (size_t)m0 * K, Bs_[0] + (size_t)n0 * K, K, tid);

    for (int c = 0; c < nch; c++) {
        int buf = c & 1;
        if (c + 1 < nch) {
            int cn = c + 1;
            int s = cn / cps, ck = (cn - s * cps) * 64;
            gemm_issue(sb, buf ^ 1, As_[s] + (size_t)m0 * K + ck,
                       Bs_[s] + (size_t)n0 * K + ck, K, tid);
            cpwait<1>();
        } else {
            cpwait<0>();
        }
        __syncthreads();
        uint32_t A = sb + buf * 2 * GAT;
        uint32_t B = A + GAT;
#pragma unroll
        for (int kk = 0; kk < 4; kk++) {
            uint32_t a[2][4];
#pragma unroll
            for (int mt = 0; mt < 2; mt++)
                ldsm4(A + (wm*32 + mt*16 + aRow) * HROWB + aHalf + kk*32, a[mt]);
            uint32_t bfr[8][2];
#pragma unroll
            for (int fp = 0; fp < 4; fp++) {
                int fi = fp * 2 + (gB >> 1);
                uint32_t r4[4];
                ldsm4(B + (wn*64 + fi*8 + (lane & 7)) * HROWB + bHalf + kk*32, r4);
                bfr[fp*2][0]   = r4[0]; bfr[fp*2][1]   = r4[1];
                bfr[fp*2+1][0] = r4[2]; bfr[fp*2+1][1] = r4[3];
            }
#pragma unroll
            for (int mt = 0; mt < 2; mt++)
#pragma unroll
                for (int f = 0; f < 8; f++)
                    mma_bf16(acc[mt][f], a[mt], bfr[f][0], bfr[f][1]);
        }
        __syncthreads();
    }

    // epilogue: lane holds (row g4 / g4+8, cols tig*2, tig*2+1) per frag
    int g4 = lane >> 2, tig = lane & 3;
#pragma unroll
    for (int mt = 0; mt < 2; mt++) {
#pragma unroll
        for (int f = 0; f < 8; f++) {
            int r0 = m0 + wm*32 + mt*16 + g4;
            int c0 = n0 + wn*64 + f*8 + tig*2;
            float b0 = bias ? bias[c0] : 0.f;
            float b1 = bias ? bias[c0+1] : 0.f;
            float2 v0; v0.x = acc[mt][f][0] + b0; v0.y = acc[mt][f][1] + b1;
            float2 v1; v1.x = acc[mt][f][2] + b0; v1.y = acc[mt][f][3] + b1;
            *(float2*)&C[(size_t)r0 * Ntot + c0] = v0;
            *(float2*)&C[(size_t)(r0 + 8) * Ntot + c0] = v1;
        }
    }
}

// ---------------- persistent LSTM with mma recurrence ----------------
// CTA owns gate rows r = g*JC+jj (24 rows of Whh). Whh split hi/lo cached in
// SMEM. h kept in global as bf16 (hi, lo), staged per 64-k chunk via cp.async.
// Per step: C[64x24] = h_hi@Whi + h_hi@Wlo + h_lo@Whi (fp32 accum), then cell.
__device__ __forceinline__ void rec_issue(uint32_t hb_addr, int buf,
                                          const __nv_bfloat16* hhi,
                                          const __nv_bfloat16* hlo,
                                          int k0, int tid)
{
    uint32_t dH = hb_addr + buf * 2 * HTILE;
    uint32_t dL = dH + HTILE;
#pragma unroll
    for (int it = 0; it < 4; it++) {
        int idx = it * 128 + tid;         // 512 granules per matrix
        int row = idx >> 3, seg = idx & 7;
        cpasync16(dH + row * HROWB + seg * 16, hhi + (size_t)row * HH + k0 + seg * 8);
        cpasync16(dL + row * HROWB + seg * 16, hlo + (size_t)row * HH + k0 + seg * 8);
    }
    cpcommit();
}

__global__ __launch_bounds__(128, 1)
void lstm_persist(const float* __restrict__ pre, const float* __restrict__ Whh,
                  __nv_bfloat16* __restrict__ hb, float* __restrict__ cst,
                  float* __restrict__ y, const float* __restrict__ res)
{
    extern __shared__ __align__(128) char rsm[];
    char* Whi = rsm;
    char* Wlo = rsm + WTILE;
    char* Hb  = rsm + 2 * WTILE;
    float* Csm = (float*)(rsm + 2 * WTILE + 4 * HTILE);

    int tid = threadIdx.x;
    int lane = tid & 31;
    int w = tid >> 5;            // 4 warps: rows w*16..w*16+15
    int j0 = blockIdx.x * JC;
    unsigned e0 = 0;
    if (tid == 0) e0 = *(volatile unsigned*)&g_epoch;

    // cache Whh slice as bf16 hi/lo. SMEM row r = gate r/JC, col j0 + r%JC.
    for (int i = tid; i < NC * HH; i += 128) {
        int r = i / HH, k = i - r * HH;
        int g = r / JC, jj = r - g * JC;
        float v = Whh[(size_t)(g * HH + j0 + jj) * HH + k];
        __nv_bfloat16 h = __float2bfloat16(v);
        ((__nv_bfloat16*)(Whi + r * WROWB))[k] = h;
        ((__nv_bfloat16*)(Wlo + r * WROWB))[k] = __float2bfloat16(v - __bfloat162float(h));
    }

    // zero h (parity 0, hi+lo) and c for owned columns
    if (tid < BB) {
        __nv_bfloat16 z = __float2bfloat16(0.f);
#pragma unroll
        for (int jj = 0; jj < JC; jj++) {
            int ci = tid * HH + j0 + jj;
            hb[ci] = z;              // parity0 hi
            hb[BBHH + ci] = z;       // parity0 lo
            cst[ci] = 0.f;
        }
    }
    grid_barrier(e0, 1);

    uint32_t hbA = smem_u32(Hb);
    uint32_t wA[2] = { smem_u32(Whi), smem_u32(Wlo) };

    // per-thread ldmatrix components
    int aRow = (lane & 15);
    int aHalf = (lane >> 4) * 16;
    int gB = lane >> 3;
    int fi01 = (gB >> 1) * 8 + (lane & 7);     // rows for fragments f0/f1
    int bHalf01 = (gB & 1) * 16;
    int row2 = 16 + (lane & 7);                // rows for fragment f2
    int bHalf2 = ((lane >> 3) & 1) * 16;
    int g4 = lane >> 2, tig = lane & 3;

    const int paA[3] = { 0, 0, 1 };
    const int paW[3] = { 0, 1, 0 };

    for (int t = 0; t < TT; t++) {
        int pin = t & 1;
        const __nv_bfloat16* hinh = hb + (size_t)(pin * 2 + 0) * BBHH;
        const __nv_bfloat16* hinl = hb + (size_t)(pin * 2 + 1) * BBHH;
        __nv_bfloat16* houth = hb + (size_t)((pin ^ 1) * 2 + 0) * BBHH;
        __nv_bfloat16* houtl = hb + (size_t)((pin ^ 1) * 2 + 1) * BBHH;

        rec_issue(hbA, 0, hinh, hinl, 0, tid);

        float acc[3][4];
#pragma unroll
        for (int f = 0; f < 3; f++)
#pragma unroll
            for (int r = 0; r < 4; r++) acc[f][r] = 0.f;

        for (int c = 0; c < NCHR; c++) {
            int buf = c & 1;
            if (c + 1 < NCHR) {
                rec_issue(hbA, buf ^ 1, hinh, hinl, (c + 1) * 64, tid);
                cpwait<1>();
            } else {
                cpwait<0>();
            }
            __syncthreads();
            uint32_t Ab[2];
            Ab[0] = hbA + buf * 2 * HTILE;
            Ab[1] = Ab[0] + HTILE;
#pragma unroll
            for (int p = 0; p < 3; p++) {
                uint32_t Abase = Ab[paA[p]];
                uint32_t Wbase = wA[paW[p]] + c * 128;
#pragma unroll
                for (int kk = 0; kk < 4; kk++) {
                    uint32_t a[4];
                    ldsm4(Abase + (w*16 + aRow) * HROWB + aHalf + kk*32, a);
                    uint32_t b01[4];
                    ldsm4(Wbase + fi01 * WROWB + bHalf01 + kk*32, b01);
                    uint32_t b2[2];
                    ldsm2(Wbase + row2 * WROWB + bHalf2 + kk*32, b2);
                    mma_bf16(acc[0], a, b01[0], b01[1]);
                    mma_bf16(acc[1], a, b01[2], b01[3]);
                    mma_bf16(acc[2], a, b2[0], b2[1]);
                }
            }
            __syncthreads();
        }

        // write gate tile to Csm: row = batch, col = gate*JC + jj (0..23)
#pragma unroll
        for (int f = 0; f < 3; f++) {
            Csm[(w*16 + g4) * 28 + f*8 + tig*2]     = acc[f][0];
            Csm[(w*16 + g4) * 28 + f*8 + tig*2 + 1] = acc[f][1];
            Csm[(w*16 + 8 + g4) * 28 + f*8 + tig*2]     = acc[f][2];
            Csm[(w*16 + 8 + g4) * 28 + f*8 + tig*2 + 1] = acc[f][3];
        }
        __syncthreads();

        // cell update: 64 b x JC cols = 384 elems, 3 per thread
#pragma unroll
        for (int r = 0; r < 3; r++) {
            int e = r * 128 + tid;
            int b = e / JC, jj = e - b * JC;
            int j = j0 + jj;
            size_t prow = ((size_t)b * TT + t) * GG;
            float gi = Csm[b*28 + 0*JC + jj] + pre[prow + 0*HH + j];
            float gf = Csm[b*28 + 1*JC + jj] + pre[prow + 1*HH + j];
            float gg = Csm[b*28 + 2*JC + jj] + pre[prow + 2*HH + j];
            float go = Csm[b*28 + 3*JC + jj] + pre[prow + 3*HH + j];
            float si = 1.0f / (1.0f + expf(-gi));
            float sf = 1.0f / (1.0f + expf(-gf));
            float so = 1.0f / (1.0f + expf(-go));
            float tg = tanhf(gg);
            int ci = b * HH + j;
            float cn = sf * cst[ci] + si * tg;
            float hn = so * tanhf(cn);
            cst[ci] = cn;
            __nv_bfloat16 hh = __float2bfloat16(hn);
            houth[ci] = hh;
            houtl[ci] = __float2bfloat16(hn - __bfloat162float(hh));
            size_t yi = ((size_t)b * TT + t) * HH + j;
            y[yi] = res ? hn + res[yi] : hn;
        }
        grid_barrier(e0, t + 2);
    }
}

// ---------------- output copy ----------------
__global__ void copy_out(float* __restrict__ out, const float* __restrict__ proj, int n)
{
    int i = blockIdx.x * blockDim.x + threadIdx.x;
    int stride = gridDim.x * blockDim.x;
    for (; i < n; i += stride) {
        int m = i / OUTD, o = i % OUTD;
        out[i] = proj[(size_t)m * 128 + o];
    }
}

// ---------------- driver ----------------
extern "C" void kernel_launch(void* const* d_in, const int* in_sizes, int n_in,
                              void* d_out, int out_size)
{
    const float* x   = (const float*)d_in[0];
    const float* Wih[3] = { (const float*)d_in[1], (const float*)d_in[4], (const float*)d_in[7] };
    const float* Whh[3] = { (const float*)d_in[2], (const float*)d_in[5], (const float*)d_in[8] };
    const float* bgt[3] = { (const float*)d_in[3], (const float*)d_in[6], (const float*)d_in[9] };
    const float* Wp  = (const float*)d_in[10];

    float *pre, *x1, *x2, *x3, *proj, *cbuf;
    __nv_bfloat16 *ah, *al, *bh, *bl, *pph, *ppl, *hb;
    cudaGetSymbolAddress((void**)&pre,  g_pre);
    cudaGetSymbolAddress((void**)&x1,   g_x1);
    cudaGetSymbolAddress((void**)&x2,   g_x2);
    cudaGetSymbolAddress((void**)&x3,   g_x3);
    cudaGetSymbolAddress((void**)&proj, g_proj);
    cudaGetSymbolAddress((void**)&cbuf, g_c);
    cudaGetSymbolAddress((void**)&hb,   g_hb);
    cudaGetSymbolAddress((void**)&ah,   g_ah);
    cudaGetSymbolAddress((void**)&al,   g_al);
    cudaGetSymbolAddress((void**)&bh,   g_bh);
    cudaGetSymbolAddress((void**)&bl,   g_bl);
    cudaGetSymbolAddress((void**)&pph,  g_ph);
    cudaGetSymbolAddress((void**)&ppl,  g_pl);

    cudaFuncSetAttribute(lstm_persist, cudaFuncAttributeMaxDynamicSharedMemorySize, RSMEM);
    cudaFuncSetAttribute(gemm_mma3, cudaFuncAttributeMaxDynamicSharedMemorySize, GSMEM);

    float* xs[3] = { x1, x2, x3 };
    const float* layerIn = x;
    int K = INF;

    for (int L = 0; L < 3; L++) {
        split_bf16<<<4096, 256>>>(layerIn, ah, al, (size_t)MM * K / 4);
        split_bf16<<<512, 256>>>(Wih[L], bh, bl, (size_t)GG * K / 4);

        dim3 grid(GG / 128, MM / 128);
        gemm_mma3<<<grid, 256, GSMEM>>>(ah, al, bh, bl, bgt[L], pre, K, GG);

        const float* res = (L > 0) ? layerIn : nullptr;
        lstm_persist<<<NCTA, 128, RSMEM>>>(pre, Whh[L], hb, cbuf, xs[L], res);

        layerIn = xs[L];
        K = HH;
    }

    // projection
    split_bf16<<<4096, 256>>>(x3, ah, al, (size_t)MM * HH / 4);
    pad_wp_split<<<96, 256>>>(pph, ppl, Wp);
    dim3 gridP(1, MM / 128);
    gemm_mma3<<<gridP, 256, GSMEM>>>(ah, al, pph, ppl, nullptr, proj, HH, 128);
    copy_out<<<1024, 256>>>((float*)d_out, proj, MM * OUTD);
}